// round 11
// baseline (speedup 1.0000x reference)
#include <cuda_runtime.h>
#include <cuda_fp16.h>
#include <math.h>
#include <stdint.h>

#define NN 8192
#define F  256
#define ALPHA_C 0.2f

// ---------------- scratch ----------------
__device__ uint32_t g_WhBh[NN / 32 * F * 16];  // fp16 Wh, B-fragment order [chunk32][n][pi]
__device__ float    g_t[2 * F];                // [tsrc | tdst] = W^T r halves
__device__ float    g_ssrc[NN];
__device__ float    g_sdst[NN];
__device__ float    g_E0[NN];
__device__ float    g_E1[NN];
__device__ float    g_c0[NN];
__device__ float    g_c1[NN];
__device__ unsigned g_gmax_enc;

// ---------------- helpers ----------------
__device__ __forceinline__ void mma_f16(float* d, const uint32_t* a, uint32_t b0, uint32_t b1) {
    asm volatile(
        "mma.sync.aligned.m16n8k16.row.col.f32.f16.f16.f32 "
        "{%0,%1,%2,%3}, {%4,%5,%6,%7}, {%8,%9}, {%0,%1,%2,%3};\n"
        : "+f"(d[0]), "+f"(d[1]), "+f"(d[2]), "+f"(d[3])
        : "r"(a[0]), "r"(a[1]), "r"(a[2]), "r"(a[3]), "r"(b0), "r"(b1));
}
__device__ __forceinline__ unsigned fenc(float f) {
    unsigned b = __float_as_uint(f);
    return (b & 0x80000000u) ? ~b : (b | 0x80000000u);
}
__device__ __forceinline__ float fdec(unsigned e) {
    unsigned b = (e & 0x80000000u) ? (e & 0x7FFFFFFFu) : ~e;
    return __uint_as_float(b);
}
#define CP16(DST, SRC) \
    asm volatile("cp.async.cg.shared.global [%0], [%1], 16;" :: "r"(DST), "l"(SRC))

// ---------------- K0: t = W^T r (both halves) ----------------
__global__ void __launch_bounds__(256) k0_t(const float* __restrict__ W,
                                            const float* __restrict__ r) {
    const int k = threadIdx.x;
    float ts = 0.f, td = 0.f;
#pragma unroll 8
    for (int n = 0; n < F; n++) {
        float w = W[(size_t)n * F + k];
        ts += w * __ldg(&r[n]);
        td += w * __ldg(&r[F + n]);
    }
    g_t[k]     = ts;
    g_t[F + k] = td;
}

// ---------------- K1: Wh = X @ W^T (fp32 compute) -> fp16 B-fragment pack only ----------------
__global__ void __launch_bounds__(256) k1_wh(const float* __restrict__ X,
                                             const float* __restrict__ W) {
    __shared__ float Xs[16][64];
    __shared__ float Ws[16][128];
    const int tid = threadIdx.x;
    const int i0  = blockIdx.x * 64;
    const int nb  = blockIdx.y * 128;
    const int ty  = tid >> 5, tx = tid & 31;
    const int r   = tid & 63, kg = tid >> 6;
    const int o   = tid & 127, kh = tid >> 7;

    float acc[8][4];
#pragma unroll
    for (int m = 0; m < 8; m++)
#pragma unroll
        for (int n = 0; n < 4; n++) acc[m][n] = 0.f;

    for (int f0 = 0; f0 < F; f0 += 16) {
        float4 xv = *(const float4*)&X[(size_t)(i0 + r) * F + f0 + kg * 4];
        Xs[kg * 4 + 0][r] = xv.x;
        Xs[kg * 4 + 1][r] = xv.y;
        Xs[kg * 4 + 2][r] = xv.z;
        Xs[kg * 4 + 3][r] = xv.w;
        const float* wp = &W[(size_t)(nb + o) * F + f0 + kh * 8];
        float4 w0 = *(const float4*)(wp + 0);
        float4 w1 = *(const float4*)(wp + 4);
        Ws[kh * 8 + 0][o] = w0.x;  Ws[kh * 8 + 1][o] = w0.y;
        Ws[kh * 8 + 2][o] = w0.z;  Ws[kh * 8 + 3][o] = w0.w;
        Ws[kh * 8 + 4][o] = w1.x;  Ws[kh * 8 + 5][o] = w1.y;
        Ws[kh * 8 + 6][o] = w1.z;  Ws[kh * 8 + 7][o] = w1.w;
        __syncthreads();
#pragma unroll
        for (int kk = 0; kk < 16; kk++) {
            float av[8], bv[4];
            *(float4*)(av + 0) = *(const float4*)&Xs[kk][ty * 8 + 0];
            *(float4*)(av + 4) = *(const float4*)&Xs[kk][ty * 8 + 4];
            *(float4*)(bv + 0) = *(const float4*)&Ws[kk][tx * 4];
#pragma unroll
            for (int m = 0; m < 8; m++)
#pragma unroll
                for (int n = 0; n < 4; n++) acc[m][n] += av[m] * bv[n];
        }
        __syncthreads();
    }
    // fp16 pack in B-fragment order (rows j = i0+ty*8+m)
    {
        const int chunk = (i0 + ty * 8) >> 5;
        const int jb    = (i0 + ty * 8) & 31;
        uint32_t* dst = g_WhBh + (size_t)chunk * (F * 16);
#pragma unroll
        for (int mp = 0; mp < 4; mp++) {
            int jl = jb + 2 * mp;
            int pi = ((jl & 7) >> 1) * 4 + ((jl >> 4) & 1) * 2 + ((jl >> 3) & 1);
#pragma unroll
            for (int c = 0; c < 4; c++) {
                __half2 h = __floats2half2_rn(acc[2 * mp][c], acc[2 * mp + 1][c]);
                dst[(size_t)(nb + tx * 4 + c) * 16 + pi] = *(const uint32_t*)&h;
            }
        }
    }
}

// ---------------- K2: scores from X @ t + fused global max ----------------
__global__ void __launch_bounds__(256) k2_scores(const float* __restrict__ X) {
    const int row  = (blockIdx.x * blockDim.x + threadIdx.x) >> 5;
    const int lane = threadIdx.x & 31;
    if (row >= NN) return;
    const float* xp = &X[(size_t)row * F];
    float ss = 0.f, sd = 0.f;
#pragma unroll
    for (int q = 0; q < 8; q++) {
        int k = lane + q * 32;
        float v = xp[k];
        ss += v * __ldg(&g_t[k]);
        sd += v * __ldg(&g_t[F + k]);
    }
#pragma unroll
    for (int o = 16; o > 0; o >>= 1) {
        ss += __shfl_xor_sync(0xffffffffu, ss, o);
        sd += __shfl_xor_sync(0xffffffffu, sd, o);
    }
    if (lane == 0) {
        g_ssrc[row] = ss;
        g_sdst[row] = sd;
        atomicMax(&g_gmax_enc, fenc(sd));
    }
}

// ---------------- K3b: stable exp tables ----------------
__global__ void __launch_bounds__(256) k3b_tables() {
    const int i = blockIdx.x * 256 + threadIdx.x;
    const float M  = fdec(g_gmax_enc);
    const float sd = g_sdst[i];
    const float si = g_ssrc[i];
    g_E0[i] = expf(sd - M);
    g_E1[i] = expf(ALPHA_C * (sd - M));
    float u  = si + M;
    float mi = (u >= 0.f) ? u : ALPHA_C * u;
    g_c0[i] = expf(u - mi);
    g_c1[i] = expf(ALPHA_C * u - mi);
}

// ---------------- K4: fp16 mma, BK=64, fully staged inputs, 32x32 warp tiles ----------------
// smem: B 2x32768 @0 ; EM 2x49152 @65536 (per-thread 96B: mask32|E0 32|E1 32) ;
//       fragA 2x8192 @163840 ; zsh @180224 ; zinv @182272
#define BBUF     32768
#define EM_OFF   65536
#define EMBUF    49152
#define FRAG_OFF 163840
#define FRAGBUF  8192
#define ZSH_OFF  180224
#define ZINV_OFF 182272
#define K4_SMEM  182528
#define NCHUNK   (NN / 64)

__global__ void __launch_bounds__(512) k4_mma(const int* __restrict__ A,
                                              float* __restrict__ out) {
    extern __shared__ char smem[];
    const uint32_t sb = (uint32_t)__cvta_generic_to_shared(smem);
    const int tid = threadIdx.x, lane = tid & 31, warp = tid >> 5;
    const int i0 = blockIdx.x * 64;
    const int g = lane >> 2, t = lane & 3;
    const int my = warp >> 3, wx = warp & 7;   // 2 x 8 warp grid (32x32 tiles)

    // ---- builder mapping: row r, 8 j's at offset jo within each 64-chunk ----
    const int r  = tid >> 3;
    const int jo = (tid & 7) * 8;
    const float c0 = g_c0[i0 + r];
    const float c1 = g_c1[i0 + r];
    char* emp = smem + EM_OFF + tid * 96;          // + s*EMBUF
    const uint32_t emd = sb + EM_OFF + tid * 96;   // cp.async dst base
    const int ks_b = jo >> 4;
    const int hi   = (jo >> 3) & 1;
    char* fb0 = smem + FRAG_OFF +
                ((((r >> 4) * 4 + ks_b) * 32 + (r & 7) * 4) * 16 + hi * 8 + ((r >> 3) & 1) * 4);
    float zp = 0.f;

    // ---- loader sources ----
    const int*      msrc0 = A + (size_t)(i0 + r) * NN + jo;
    const uint32_t* bsrc  = g_WhBh + (size_t)(tid >> 1) * 16 + (size_t)(tid & 1) * 8;
    const uint32_t  bdst  = sb + (tid >> 1) * 64 + (tid & 1) * 32;

    float acc[2][4][4];
#pragma unroll
    for (int m = 0; m < 2; m++)
#pragma unroll
        for (int u = 0; u < 4; u++)
#pragma unroll
            for (int q = 0; q < 4; q++) acc[m][u][q] = 0.f;

#define ISSUE_STAGE(CIDX, S) do {                                              \
        const uint32_t* sB = bsrc + (size_t)(CIDX) * 8192;                     \
        uint32_t dB = bdst + (S) * BBUF;                                       \
        CP16(dB, sB);                                                          \
        CP16(dB + 16, sB + 4);                                                 \
        CP16(dB + 16384, sB + 4096);                                           \
        CP16(dB + 16384 + 16, sB + 4100);                                      \
        uint32_t dE = emd + (S) * EMBUF;                                       \
        const int* sM = msrc0 + (CIDX) * 64;                                   \
        CP16(dE + 0,  sM);                                                     \
        CP16(dE + 16, sM + 4);                                                 \
        CP16(dE + 32, g_E0 + (CIDX) * 64 + jo);                                \
        CP16(dE + 48, g_E0 + (CIDX) * 64 + jo + 4);                            \
        CP16(dE + 64, g_E1 + (CIDX) * 64 + jo);                                \
        CP16(dE + 80, g_E1 + (CIDX) * 64 + jo + 4);                            \
        asm volatile("cp.async.commit_group;");                                \
    } while (0)

#define BUILD_CHUNK(S) do {                                                    \
        char* em = emp + (S) * EMBUF;                                          \
        int4   ma  = *(const int4*)(em + 0);                                   \
        int4   mb  = *(const int4*)(em + 16);                                  \
        float4 e0a = *(const float4*)(em + 32);                                \
        float4 e0b = *(const float4*)(em + 48);                                \
        float4 e1a = *(const float4*)(em + 64);                                \
        float4 e1b = *(const float4*)(em + 80);                                \
        float w0 = fmaxf(c0 * e0a.x, c1 * e1a.x);                              \
        float w1 = fmaxf(c0 * e0a.y, c1 * e1a.y);                              \
        float w2 = fmaxf(c0 * e0a.z, c1 * e1a.z);                              \
        float w3 = fmaxf(c0 * e0a.w, c1 * e1a.w);                              \
        float w4 = fmaxf(c0 * e0b.x, c1 * e1b.x);                              \
        float w5 = fmaxf(c0 * e0b.y, c1 * e1b.y);                              \
        float w6 = fmaxf(c0 * e0b.z, c1 * e1b.z);                              \
        float w7 = fmaxf(c0 * e0b.w, c1 * e1b.w);                              \
        __half2 p0 = __floats2half2_rn(w0, w1);                                \
        __half2 p1 = __floats2half2_rn(w2, w3);                                \
        __half2 p2 = __floats2half2_rn(w4, w5);                                \
        __half2 p3 = __floats2half2_rn(w6, w7);                                \
        uint32_t q0 = (*(const uint32_t*)&p0) &                                \
            ((ma.x ? 0x0000FFFFu : 0u) | (ma.y ? 0xFFFF0000u : 0u));           \
        uint32_t q1 = (*(const uint32_t*)&p1) &                                \
            ((ma.z ? 0x0000FFFFu : 0u) | (ma.w ? 0xFFFF0000u : 0u));           \
        uint32_t q2 = (*(const uint32_t*)&p2) &                                \
            ((mb.x ? 0x0000FFFFu : 0u) | (mb.y ? 0xFFFF0000u : 0u));           \
        uint32_t q3 = (*(const uint32_t*)&p3) &                                \
            ((mb.z ? 0x0000FFFFu : 0u) | (mb.w ? 0xFFFF0000u : 0u));           \
        char* fb = fb0 + (S) * FRAGBUF;                                        \
        *(uint32_t*)(fb)      = q0;                                            \
        *(uint32_t*)(fb + 16) = q1;                                            \
        *(uint32_t*)(fb + 32) = q2;                                            \
        *(uint32_t*)(fb + 48) = q3;                                            \
        float2 z0 = __half22float2(*(const __half2*)&q0);                      \
        float2 z1 = __half22float2(*(const __half2*)&q1);                      \
        float2 z2 = __half22float2(*(const __half2*)&q2);                      \
        float2 z3 = __half22float2(*(const __half2*)&q3);                      \
        zp += ((z0.x + z0.y) + (z1.x + z1.y)) + ((z2.x + z2.y) + (z3.x + z3.y)); \
    } while (0)

    // ---- prologue ----
    ISSUE_STAGE(0, 0);
    asm volatile("cp.async.wait_group 0;");

    for (int it = 0; it < NCHUNK; ++it) {
        const int s = it & 1;

        // build chunk it from staged inputs (same-thread cp.async data)
        BUILD_CHUNK(s);

        __syncthreads();   // frag(it) + B(it) visible to all; bufs s^1 free

        if (it < NCHUNK - 1) ISSUE_STAGE(it + 1, s ^ 1);

        // ---- MMA chunk it ----
        {
            const char* bb = smem + s * BBUF;
            const char* fa = smem + FRAG_OFF + s * FRAGBUF;
            uint4 aqA[4], aqB[4];
#pragma unroll
            for (int ks = 0; ks < 4; ks++) {
                aqA[ks] = *(const uint4*)(fa + (((2 * my + 0) * 4 + ks) * 32 + lane) * 16);
                aqB[ks] = *(const uint4*)(fa + (((2 * my + 1) * 4 + ks) * 32 + lane) * 16);
            }
#pragma unroll
            for (int u = 0; u < 4; u++) {
                const int boff = (wx * 32 + u * 8 + g) * 64 + t * 16;
                uint4 bq0 = *(const uint4*)(bb + boff);
                uint4 bq1 = *(const uint4*)(bb + 16384 + boff);
                mma_f16(acc[0][u], (const uint32_t*)&aqA[0], bq0.x, bq0.y);
                mma_f16(acc[0][u], (const uint32_t*)&aqA[1], bq0.z, bq0.w);
                mma_f16(acc[0][u], (const uint32_t*)&aqA[2], bq1.x, bq1.y);
                mma_f16(acc[0][u], (const uint32_t*)&aqA[3], bq1.z, bq1.w);
                mma_f16(acc[1][u], (const uint32_t*)&aqB[0], bq0.x, bq0.y);
                mma_f16(acc[1][u], (const uint32_t*)&aqB[1], bq0.z, bq0.w);
                mma_f16(acc[1][u], (const uint32_t*)&aqB[2], bq1.x, bq1.y);
                mma_f16(acc[1][u], (const uint32_t*)&aqB[3], bq1.z, bq1.w);
            }
        }

        if (it < NCHUNK - 1) asm volatile("cp.async.wait_group 0;");
    }
#undef BUILD_CHUNK
#undef ISSUE_STAGE

    // ---- Z reduce (deterministic) ----
    float* zsh  = (float*)(smem + ZSH_OFF);
    float* zinv = (float*)(smem + ZINV_OFF);
    __syncthreads();
    zsh[tid] = zp;
    __syncthreads();
    if (tid < 64) {
        const float* p = zsh + tid * 8;
        float z = ((p[0] + p[1]) + (p[2] + p[3])) + ((p[4] + p[5]) + (p[6] + p[7]));
        zinv[tid] = 1.0f / z;
    }
    __syncthreads();

    // ---- epilogue: /Z, exact GELU, store ----
#pragma unroll
    for (int mt = 0; mt < 2; mt++) {
        const int rr = my * 32 + mt * 16 + g;
        const float zi0 = zinv[rr];
        const float zi1 = zinv[rr + 8];
#pragma unroll
        for (int u = 0; u < 4; u++) {
            int col = wx * 32 + u * 8 + t * 2;
            float x0 = acc[mt][u][0] * zi0;
            float x1 = acc[mt][u][1] * zi0;
            float x2 = acc[mt][u][2] * zi1;
            float x3 = acc[mt][u][3] * zi1;
            float g0 = 0.5f * x0 * (1.0f + erff(x0 * 0.70710678118654752f));
            float g1 = 0.5f * x1 * (1.0f + erff(x1 * 0.70710678118654752f));
            float g2 = 0.5f * x2 * (1.0f + erff(x2 * 0.70710678118654752f));
            float g3 = 0.5f * x3 * (1.0f + erff(x3 * 0.70710678118654752f));
            *(float2*)&out[(size_t)(i0 + rr) * F + col]     = make_float2(g0, g1);
            *(float2*)&out[(size_t)(i0 + rr + 8) * F + col] = make_float2(g2, g3);
        }
    }
}

// ---------------- launch ----------------
extern "C" void kernel_launch(void* const* d_in, const int* in_sizes, int n_in,
                              void* d_out, int out_size) {
    (void)in_sizes; (void)n_in; (void)out_size;
    const float* X = (const float*)d_in[0];
    const int*   A = (const int*)d_in[1];
    const float* W = (const float*)d_in[2];
    const float* r = (const float*)d_in[3];
    float* out = (float*)d_out;

    cudaFuncSetAttribute(k4_mma, cudaFuncAttributeMaxDynamicSharedMemorySize, K4_SMEM);

    k0_t<<<1, 256>>>(W, r);
    k1_wh<<<dim3(NN / 64, 2), 256>>>(X, W);
    k2_scores<<<(NN * 32) / 256, 256>>>(X);
    k3b_tables<<<NN / 256, 256>>>();
    k4_mma<<<NN / 64, 512, K4_SMEM>>>(A, out);
}

// round 12
// speedup vs baseline: 1.0074x; 1.0074x over previous
#include <cuda_runtime.h>
#include <cuda_fp16.h>
#include <math.h>
#include <stdint.h>

#define NN 8192
#define F  256
#define ALPHA_C 0.2f

// ---------------- scratch ----------------
__device__ uint32_t g_WhBh[NN / 32 * F * 16];  // fp16 Wh, B-fragment order [chunk32][n][pi]
__device__ float    g_t[2 * F];                // [tsrc | tdst] = W^T r halves
__device__ float    g_ssrc[NN];
__device__ float    g_sdst[NN];
__device__ float    g_E0[NN];
__device__ float    g_E1[NN];
__device__ float    g_c0[NN];
__device__ float    g_c1[NN];
__device__ unsigned g_gmax_enc;

// ---------------- helpers ----------------
__device__ __forceinline__ void mma_f16(float* d, const uint32_t* a, uint32_t b0, uint32_t b1) {
    asm volatile(
        "mma.sync.aligned.m16n8k16.row.col.f32.f16.f16.f32 "
        "{%0,%1,%2,%3}, {%4,%5,%6,%7}, {%8,%9}, {%0,%1,%2,%3};\n"
        : "+f"(d[0]), "+f"(d[1]), "+f"(d[2]), "+f"(d[3])
        : "r"(a[0]), "r"(a[1]), "r"(a[2]), "r"(a[3]), "r"(b0), "r"(b1));
}
__device__ __forceinline__ unsigned fenc(float f) {
    unsigned b = __float_as_uint(f);
    return (b & 0x80000000u) ? ~b : (b | 0x80000000u);
}
__device__ __forceinline__ float fdec(unsigned e) {
    unsigned b = (e & 0x80000000u) ? (e & 0x7FFFFFFFu) : ~e;
    return __uint_as_float(b);
}
#define CP16(DST, SRC) \
    asm volatile("cp.async.cg.shared.global [%0], [%1], 16;" :: "r"(DST), "l"(SRC))

// ---------------- K0: t = W^T r (both halves) ----------------
__global__ void __launch_bounds__(256) k0_t(const float* __restrict__ W,
                                            const float* __restrict__ r) {
    const int k = threadIdx.x;
    float ts = 0.f, td = 0.f;
#pragma unroll 8
    for (int n = 0; n < F; n++) {
        float w = W[(size_t)n * F + k];
        ts += w * __ldg(&r[n]);
        td += w * __ldg(&r[F + n]);
    }
    g_t[k]     = ts;
    g_t[F + k] = td;
}

// ---------------- K1: Wh = X @ W^T (fp32 compute) -> fp16 B-fragment pack only ----------------
__global__ void __launch_bounds__(256) k1_wh(const float* __restrict__ X,
                                             const float* __restrict__ W) {
    __shared__ float Xs[16][64];
    __shared__ float Ws[16][128];
    const int tid = threadIdx.x;
    const int i0  = blockIdx.x * 64;
    const int nb  = blockIdx.y * 128;
    const int ty  = tid >> 5, tx = tid & 31;
    const int r   = tid & 63, kg = tid >> 6;
    const int o   = tid & 127, kh = tid >> 7;

    float acc[8][4];
#pragma unroll
    for (int m = 0; m < 8; m++)
#pragma unroll
        for (int n = 0; n < 4; n++) acc[m][n] = 0.f;

    for (int f0 = 0; f0 < F; f0 += 16) {
        float4 xv = *(const float4*)&X[(size_t)(i0 + r) * F + f0 + kg * 4];
        Xs[kg * 4 + 0][r] = xv.x;
        Xs[kg * 4 + 1][r] = xv.y;
        Xs[kg * 4 + 2][r] = xv.z;
        Xs[kg * 4 + 3][r] = xv.w;
        const float* wp = &W[(size_t)(nb + o) * F + f0 + kh * 8];
        float4 w0 = *(const float4*)(wp + 0);
        float4 w1 = *(const float4*)(wp + 4);
        Ws[kh * 8 + 0][o] = w0.x;  Ws[kh * 8 + 1][o] = w0.y;
        Ws[kh * 8 + 2][o] = w0.z;  Ws[kh * 8 + 3][o] = w0.w;
        Ws[kh * 8 + 4][o] = w1.x;  Ws[kh * 8 + 5][o] = w1.y;
        Ws[kh * 8 + 6][o] = w1.z;  Ws[kh * 8 + 7][o] = w1.w;
        __syncthreads();
#pragma unroll
        for (int kk = 0; kk < 16; kk++) {
            float av[8], bv[4];
            *(float4*)(av + 0) = *(const float4*)&Xs[kk][ty * 8 + 0];
            *(float4*)(av + 4) = *(const float4*)&Xs[kk][ty * 8 + 4];
            *(float4*)(bv + 0) = *(const float4*)&Ws[kk][tx * 4];
#pragma unroll
            for (int m = 0; m < 8; m++)
#pragma unroll
                for (int n = 0; n < 4; n++) acc[m][n] += av[m] * bv[n];
        }
        __syncthreads();
    }
    // fp16 pack in B-fragment order (rows j = i0+ty*8+m)
    {
        const int chunk = (i0 + ty * 8) >> 5;
        const int jb    = (i0 + ty * 8) & 31;
        uint32_t* dst = g_WhBh + (size_t)chunk * (F * 16);
#pragma unroll
        for (int mp = 0; mp < 4; mp++) {
            int jl = jb + 2 * mp;
            int pi = ((jl & 7) >> 1) * 4 + ((jl >> 4) & 1) * 2 + ((jl >> 3) & 1);
#pragma unroll
            for (int c = 0; c < 4; c++) {
                __half2 h = __floats2half2_rn(acc[2 * mp][c], acc[2 * mp + 1][c]);
                dst[(size_t)(nb + tx * 4 + c) * 16 + pi] = *(const uint32_t*)&h;
            }
        }
    }
}

// ---------------- K2: scores from X @ t + fused global max ----------------
__global__ void __launch_bounds__(256) k2_scores(const float* __restrict__ X) {
    const int row  = (blockIdx.x * blockDim.x + threadIdx.x) >> 5;
    const int lane = threadIdx.x & 31;
    if (row >= NN) return;
    const float* xp = &X[(size_t)row * F];
    float ss = 0.f, sd = 0.f;
#pragma unroll
    for (int q = 0; q < 8; q++) {
        int k = lane + q * 32;
        float v = xp[k];
        ss += v * __ldg(&g_t[k]);
        sd += v * __ldg(&g_t[F + k]);
    }
#pragma unroll
    for (int o = 16; o > 0; o >>= 1) {
        ss += __shfl_xor_sync(0xffffffffu, ss, o);
        sd += __shfl_xor_sync(0xffffffffu, sd, o);
    }
    if (lane == 0) {
        g_ssrc[row] = ss;
        g_sdst[row] = sd;
        atomicMax(&g_gmax_enc, fenc(sd));
    }
}

// ---------------- K3b: stable exp tables ----------------
__global__ void __launch_bounds__(256) k3b_tables() {
    const int i = blockIdx.x * 256 + threadIdx.x;
    const float M  = fdec(g_gmax_enc);
    const float sd = g_sdst[i];
    const float si = g_ssrc[i];
    g_E0[i] = expf(sd - M);
    g_E1[i] = expf(ALPHA_C * (sd - M));
    float u  = si + M;
    float mi = (u >= 0.f) ? u : ALPHA_C * u;
    g_c0[i] = expf(u - mi);
    g_c1[i] = expf(ALPHA_C * u - mi);
}

// ---------------- K4: fp16 mma, BK=64, fully staged inputs, 32x32 warp tiles ----------------
// smem: B 2x32768 @0 ; EM 2x49152 @65536 (per-thread 96B: mask32|E0 32|E1 32) ;
//       fragA 2x8192 @163840 ; zsh @180224 ; zinv @182272
#define BBUF     32768
#define EM_OFF   65536
#define EMBUF    49152
#define FRAG_OFF 163840
#define FRAGBUF  8192
#define ZSH_OFF  180224
#define ZINV_OFF 182272
#define K4_SMEM  182528
#define NCHUNK   (NN / 64)

__global__ void __launch_bounds__(512) k4_mma(const int* __restrict__ A,
                                              float* __restrict__ out) {
    extern __shared__ char smem[];
    const uint32_t sb = (uint32_t)__cvta_generic_to_shared(smem);
    const int tid = threadIdx.x, lane = tid & 31, warp = tid >> 5;
    const int i0 = blockIdx.x * 64;
    const int g = lane >> 2, t = lane & 3;
    const int my = warp >> 3, wx = warp & 7;   // 2 x 8 warp grid (32x32 tiles)

    // ---- builder mapping: row r, 8 j's at offset jo within each 64-chunk ----
    const int r  = tid >> 3;
    const int jo = (tid & 7) * 8;
    const float c0 = g_c0[i0 + r];
    const float c1 = g_c1[i0 + r];
    char* emp = smem + EM_OFF + tid * 96;          // + s*EMBUF
    const uint32_t emd = sb + EM_OFF + tid * 96;   // cp.async dst base
    const int ks_b = jo >> 4;
    const int hi   = (jo >> 3) & 1;
    char* fb0 = smem + FRAG_OFF +
                ((((r >> 4) * 4 + ks_b) * 32 + (r & 7) * 4) * 16 + hi * 8 + ((r >> 3) & 1) * 4);
    float zp = 0.f;

    // ---- loader sources ----
    const int*      msrc0 = A + (size_t)(i0 + r) * NN + jo;
    const uint32_t* bsrc  = g_WhBh + (size_t)(tid >> 1) * 16 + (size_t)(tid & 1) * 8;
    const uint32_t  bdst  = sb + (tid >> 1) * 64 + (tid & 1) * 32;

    float acc[2][4][4];
#pragma unroll
    for (int m = 0; m < 2; m++)
#pragma unroll
        for (int u = 0; u < 4; u++)
#pragma unroll
            for (int q = 0; q < 4; q++) acc[m][u][q] = 0.f;

#define ISSUE_STAGE(CIDX, S) do {                                              \
        const uint32_t* sB = bsrc + (size_t)(CIDX) * 8192;                     \
        uint32_t dB = bdst + (S) * BBUF;                                       \
        CP16(dB, sB);                                                          \
        CP16(dB + 16, sB + 4);                                                 \
        CP16(dB + 16384, sB + 4096);                                           \
        CP16(dB + 16384 + 16, sB + 4100);                                      \
        uint32_t dE = emd + (S) * EMBUF;                                       \
        const int* sM = msrc0 + (CIDX) * 64;                                   \
        CP16(dE + 0,  sM);                                                     \
        CP16(dE + 16, sM + 4);                                                 \
        CP16(dE + 32, g_E0 + (CIDX) * 64 + jo);                                \
        CP16(dE + 48, g_E0 + (CIDX) * 64 + jo + 4);                            \
        CP16(dE + 64, g_E1 + (CIDX) * 64 + jo);                                \
        CP16(dE + 80, g_E1 + (CIDX) * 64 + jo + 4);                            \
        asm volatile("cp.async.commit_group;");                                \
    } while (0)

#define BUILD_CHUNK(S) do {                                                    \
        char* em = emp + (S) * EMBUF;                                          \
        int4   ma  = *(const int4*)(em + 0);                                   \
        int4   mb  = *(const int4*)(em + 16);                                  \
        float4 e0a = *(const float4*)(em + 32);                                \
        float4 e0b = *(const float4*)(em + 48);                                \
        float4 e1a = *(const float4*)(em + 64);                                \
        float4 e1b = *(const float4*)(em + 80);                                \
        float w0 = fmaxf(c0 * e0a.x, c1 * e1a.x);                              \
        float w1 = fmaxf(c0 * e0a.y, c1 * e1a.y);                              \
        float w2 = fmaxf(c0 * e0a.z, c1 * e1a.z);                              \
        float w3 = fmaxf(c0 * e0a.w, c1 * e1a.w);                              \
        float w4 = fmaxf(c0 * e0b.x, c1 * e1b.x);                              \
        float w5 = fmaxf(c0 * e0b.y, c1 * e1b.y);                              \
        float w6 = fmaxf(c0 * e0b.z, c1 * e1b.z);                              \
        float w7 = fmaxf(c0 * e0b.w, c1 * e1b.w);                              \
        __half2 p0 = __floats2half2_rn(w0, w1);                                \
        __half2 p1 = __floats2half2_rn(w2, w3);                                \
        __half2 p2 = __floats2half2_rn(w4, w5);                                \
        __half2 p3 = __floats2half2_rn(w6, w7);                                \
        uint32_t q0 = (*(const uint32_t*)&p0) &                                \
            ((ma.x ? 0x0000FFFFu : 0u) | (ma.y ? 0xFFFF0000u : 0u));           \
        uint32_t q1 = (*(const uint32_t*)&p1) &                                \
            ((ma.z ? 0x0000FFFFu : 0u) | (ma.w ? 0xFFFF0000u : 0u));           \
        uint32_t q2 = (*(const uint32_t*)&p2) &                                \
            ((mb.x ? 0x0000FFFFu : 0u) | (mb.y ? 0xFFFF0000u : 0u));           \
        uint32_t q3 = (*(const uint32_t*)&p3) &                                \
            ((mb.z ? 0x0000FFFFu : 0u) | (mb.w ? 0xFFFF0000u : 0u));           \
        char* fb = fb0 + (S) * FRAGBUF;                                        \
        *(uint32_t*)(fb)      = q0;                                            \
        *(uint32_t*)(fb + 16) = q1;                                            \
        *(uint32_t*)(fb + 32) = q2;                                            \
        *(uint32_t*)(fb + 48) = q3;                                            \
        float2 z0 = __half22float2(*(const __half2*)&q0);                      \
        float2 z1 = __half22float2(*(const __half2*)&q1);                      \
        float2 z2 = __half22float2(*(const __half2*)&q2);                      \
        float2 z3 = __half22float2(*(const __half2*)&q3);                      \
        zp += ((z0.x + z0.y) + (z1.x + z1.y)) + ((z2.x + z2.y) + (z3.x + z3.y)); \
    } while (0)

    // ---- prologue ----
    ISSUE_STAGE(0, 0);
    asm volatile("cp.async.wait_group 0;");

    for (int it = 0; it < NCHUNK; ++it) {
        const int s = it & 1;

        // build chunk it from staged inputs (same-thread cp.async data)
        BUILD_CHUNK(s);

        __syncthreads();   // frag(it) + B(it) visible to all; bufs s^1 free

        if (it < NCHUNK - 1) ISSUE_STAGE(it + 1, s ^ 1);

        // ---- MMA chunk it ----
        {
            const char* bb = smem + s * BBUF;
            const char* fa = smem + FRAG_OFF + s * FRAGBUF;
            uint4 aqA[4], aqB[4];
#pragma unroll
            for (int ks = 0; ks < 4; ks++) {
                aqA[ks] = *(const uint4*)(fa + (((2 * my + 0) * 4 + ks) * 32 + lane) * 16);
                aqB[ks] = *(const uint4*)(fa + (((2 * my + 1) * 4 + ks) * 32 + lane) * 16);
            }
#pragma unroll
            for (int u = 0; u < 4; u++) {
                const int boff = (wx * 32 + u * 8 + g) * 64 + t * 16;
                uint4 bq0 = *(const uint4*)(bb + boff);
                uint4 bq1 = *(const uint4*)(bb + 16384 + boff);
                mma_f16(acc[0][u], (const uint32_t*)&aqA[0], bq0.x, bq0.y);
                mma_f16(acc[0][u], (const uint32_t*)&aqA[1], bq0.z, bq0.w);
                mma_f16(acc[0][u], (const uint32_t*)&aqA[2], bq1.x, bq1.y);
                mma_f16(acc[0][u], (const uint32_t*)&aqA[3], bq1.z, bq1.w);
                mma_f16(acc[1][u], (const uint32_t*)&aqB[0], bq0.x, bq0.y);
                mma_f16(acc[1][u], (const uint32_t*)&aqB[1], bq0.z, bq0.w);
                mma_f16(acc[1][u], (const uint32_t*)&aqB[2], bq1.x, bq1.y);
                mma_f16(acc[1][u], (const uint32_t*)&aqB[3], bq1.z, bq1.w);
            }
        }

        if (it < NCHUNK - 1) asm volatile("cp.async.wait_group 0;");
    }
#undef BUILD_CHUNK
#undef ISSUE_STAGE

    // ---- Z reduce (deterministic) ----
    float* zsh  = (float*)(smem + ZSH_OFF);
    float* zinv = (float*)(smem + ZINV_OFF);
    __syncthreads();
    zsh[tid] = zp;
    __syncthreads();
    if (tid < 64) {
        const float* p = zsh + tid * 8;
        float z = ((p[0] + p[1]) + (p[2] + p[3])) + ((p[4] + p[5]) + (p[6] + p[7]));
        zinv[tid] = 1.0f / z;
    }
    __syncthreads();

    // ---- epilogue: /Z, exact GELU, store ----
#pragma unroll
    for (int mt = 0; mt < 2; mt++) {
        const int rr = my * 32 + mt * 16 + g;
        const float zi0 = zinv[rr];
        const float zi1 = zinv[rr + 8];
#pragma unroll
        for (int u = 0; u < 4; u++) {
            int col = wx * 32 + u * 8 + t * 2;
            float x0 = acc[mt][u][0] * zi0;
            float x1 = acc[mt][u][1] * zi0;
            float x2 = acc[mt][u][2] * zi1;
            float x3 = acc[mt][u][3] * zi1;
            float g0 = 0.5f * x0 * (1.0f + erff(x0 * 0.70710678118654752f));
            float g1 = 0.5f * x1 * (1.0f + erff(x1 * 0.70710678118654752f));
            float g2 = 0.5f * x2 * (1.0f + erff(x2 * 0.70710678118654752f));
            float g3 = 0.5f * x3 * (1.0f + erff(x3 * 0.70710678118654752f));
            *(float2*)&out[(size_t)(i0 + rr) * F + col]     = make_float2(g0, g1);
            *(float2*)&out[(size_t)(i0 + rr + 8) * F + col] = make_float2(g2, g3);
        }
    }
}

// ---------------- launch ----------------
extern "C" void kernel_launch(void* const* d_in, const int* in_sizes, int n_in,
                              void* d_out, int out_size) {
    (void)in_sizes; (void)n_in; (void)out_size;
    const float* X = (const float*)d_in[0];
    const int*   A = (const int*)d_in[1];
    const float* W = (const float*)d_in[2];
    const float* r = (const float*)d_in[3];
    float* out = (float*)d_out;

    cudaFuncSetAttribute(k4_mma, cudaFuncAttributeMaxDynamicSharedMemorySize, K4_SMEM);

    k0_t<<<1, 256>>>(W, r);
    k1_wh<<<dim3(NN / 64, 2), 256>>>(X, W);
    k2_scores<<<(NN * 32) / 256, 256>>>(X);
    k3b_tables<<<NN / 256, 256>>>();
    k4_mma<<<NN / 64, 512, K4_SMEM>>>(A, out);
}